// round 16
// baseline (speedup 1.0000x reference)
#include <cuda_runtime.h>
#include <math.h>

#define BSZ 256
#define IND 64
#define HID 128
#define NB 50
#define S1 51
#define ROWS (S1 * S1)            // 2601
#define SEGROW 272                // interleaved A/B row: 34 * (A4 + B4) floats
#define NK4 34
#define SEGB (129 * SEGROW)       // 35088 floats per b
#define CPB 4
#define PPC ((ROWS + CPB - 1) / CPB)   // 651
#define PR  326                   // points per scatter-warp in build (8 warps)
#define NIT 11                    // ceil(PR/32)
#define SMAX 36                   // max segment rows staged per strip
#define TH0 0.06283185307179586f  // pi/50

// ---------------- global scratch ----------------
__device__ int   g_nposp;
__device__ __align__(16) float g_AB[BSZ * SEGB];   // ~36 MB interleaved A/B
__device__ float4 g_meta[BSZ * ROWS];
__device__ int   g_offs[BSZ * 130];
__device__ float g_part[BSZ * CPB];
__device__ float g_osc[BSZ * 2];
__device__ int   g_done[BSZ];

__device__ __forceinline__ int seg_of(float s, const float* bp_s) {
    int g = 0;
    #pragma unroll
    for (int stp = 64; stp >= 1; stp >>= 1) {
        int cand = g + stp;
        if (cand <= 128 && bp_s[cand - 1] < s) g = cand;
    }
    return g;
}

// ===================== build =====================
__global__ void __launch_bounds__(256, 3)
build_kernel(const float* __restrict__ x,   const float* __restrict__ h,
             const float* __restrict__ iw0, const float* __restrict__ ib0,
             const float* __restrict__ iw1, const float* __restrict__ ib1,
             const float* __restrict__ iw2,
             const float* __restrict__ nw0, const float* __restrict__ nb0,
             const float* __restrict__ nw1, const float* __restrict__ nb1,
             const float* __restrict__ nw2, const float* __restrict__ nb2)
{
    __shared__ float h_s[64];
    __shared__ float base_s[HID];
    __shared__ float w0_s[HID];
    __shared__ float bp_s[HID];
    __shared__ int   mi_s[HID];
    __shared__ float iw2_s[HID];
    __shared__ int   iperm_s[HID];
    __shared__ float a_s[HID];
    __shared__ float a2_s[HID];
    __shared__ float red_s[8];
    __shared__ float steps_s[S1 + 1];
    __shared__ float cc_s[S1 + 1];
    __shared__ float redx_s[256];
    __shared__ int   cnt2[8 * 132];
    __shared__ int   woff[8 * 132];
    __shared__ int   offs_s[132];
    __shared__ int   wc_s[4];
    __shared__ int   npos_s, nposp_s;
    __shared__ float xmax_s;

    const int tx = threadIdx.x;
    const int warp = tx >> 5, lane = tx & 31;
    const int b  = blockIdx.x;
    const float xb = x[b];

    if (tx < IND - 1) h_s[tx] = h[b * (IND - 1) + tx];
    if (tx < HID) iw2_s[tx] = iw2[tx];
    for (int i = tx; i < 8 * 132; i += 256) cnt2[i] = 0;
    if (tx == 0) g_done[b] = 0;

    // xmax
    redx_s[tx] = x[tx];
    __syncthreads();
    for (int o = 128; o > 0; o >>= 1) {
        if (tx < o) redx_s[tx] = fmaxf(redx_s[tx], redx_s[tx + o]);
        __syncthreads();
    }
    if (tx == 0) xmax_s = fmaxf(redx_s[0], 0.0f) + 10.0f;

    // steps + cc
    if (tx < S1) steps_s[tx] = cosf((float)tx * TH0);
    __syncthreads();
    if (tx < S1) {
        float sv = steps_s[tx];
        float c1 = fmaf(2.0f * sv, sv, -1.0f);
        float cm2 = 1.0f, cm1 = c1;
        float sum = 1.0f;
        #pragma unroll
        for (int ie = 1; ie <= 25; ++ie) {
            float cv = (ie == 1) ? c1 : fmaf(2.0f * c1, cm1, -cm2);
            if (ie > 1) { cm2 = cm1; cm1 = cv; }
            float W = 2.0f / (1.0f - 4.0f * (float)(ie * ie));
            sum = fmaf(cv, W, sum);
        }
        float v = sum * (2.0f / (float)NB);
        if (tx == 0 || tx == NB) v *= 0.5f;
        cc_s[tx] = v;
    }

    // iperm via ballot scan
    {
        bool pos = false; unsigned bal = 0;
        if (tx < HID) {
            pos = (iw2_s[tx] >= 0.0f);
            bal = __ballot_sync(0xffffffffu, pos);
            if (lane == 0) wc_s[warp] = __popc(bal);
        }
        __syncthreads();
        if (tx == 0) {
            int np = wc_s[0] + wc_s[1] + wc_s[2] + wc_s[3];
            npos_s = np;
            nposp_s = (np + 3) & ~3;
            if (b == 0) g_nposp = nposp_s;
        }
        __syncthreads();
        if (tx < HID) {
            unsigned lt = (1u << lane) - 1u;
            int posbef = __popc(bal & lt);
            int prefpos = 0;
            #pragma unroll
            for (int wi = 0; wi < 4; ++wi) if (wi < warp) prefpos += wc_s[wi];
            int slot;
            if (pos) slot = prefpos + posbef;
            else     slot = nposp_s + (warp * 32 - prefpos) + (lane - posbef);
            iperm_s[tx] = slot;
        }
    }

    const float xmax = xmax_s;
    const int npos  = npos_s;
    const int nposp = nposp_s;

    // base/breakpoints (tx<128) | nmlp layer0 (128..255)
    if (tx < HID) {
        float acc = ib0[tx];
        #pragma unroll 7
        for (int d = 0; d < IND - 1; ++d)
            acc = fmaf(h_s[d], iw0[(d + 1) * HID + tx], acc);
        base_s[tx] = acc;
        float w0m = iw0[tx];
        w0_s[tx] = w0m;
        float ss;
        if (w0m != 0.0f) ss = -acc / w0m;
        else ss = (acc > 0.0f) ? __int_as_float(0x7f800000) : __int_as_float(0xff800000);
        bp_s[tx] = ss;
    } else {
        int k = tx - 128;
        float acc = nb0[k];
        #pragma unroll 7
        for (int d = 0; d < IND - 1; ++d)
            acc = fmaf(h_s[d], nw0[d * HID + k], acc);
        a_s[k] = fmaxf(acc, 0.0f);
    }
    __syncthreads();
    if (tx < HID) {
        float acc = nb1[tx];
        #pragma unroll 8
        for (int m = 0; m < HID; ++m)
            acc = fmaf(a_s[m], nw1[m * HID + tx], acc);
        a2_s[tx] = fmaxf(acc, 0.0f);
    }
    __syncthreads();
    {
        int o  = tx >> 7;
        int n2 = tx & 127;
        float p = a2_s[n2] * nw2[n2 * 2 + o];
        #pragma unroll
        for (int off = 16; off >= 1; off >>= 1)
            p += __shfl_xor_sync(0xffffffffu, p, off);
        if (lane == 0) red_s[warp] = p;
    }
    __syncthreads();
    if (tx == 0)   g_osc[2 * b]     = nb2[0] + ((red_s[0] + red_s[1]) + (red_s[2] + red_s[3]));
    if (tx == 128) g_osc[2 * b + 1] = nb2[1] + ((red_s[4] + red_s[5]) + (red_s[6] + red_s[7]));

    // ---- bitonic sort of 128 breakpoints: registers + shfl, 3 smem steps ----
    {
        float v = 0.0f; int idx = 0;
        if (tx < 128) { v = bp_s[tx]; idx = tx; }

        #define CMP_SHFL(kkc, jc) { \
            float ov = __shfl_xor_sync(0xffffffffu, v, (jc)); \
            int oidx = __shfl_xor_sync(0xffffffffu, idx, (jc)); \
            bool amLow = ((tx & (jc)) == 0); \
            float lv = amLow ? v : ov, hv = amLow ? ov : v; \
            bool up = ((tx & (kkc)) == 0); \
            bool sw = ((lv > hv) == up); \
            if (sw) { v = ov; idx = oidx; } }

        if (tx < 128) {
            CMP_SHFL(2, 1)
            CMP_SHFL(4, 2) CMP_SHFL(4, 1)
            CMP_SHFL(8, 4) CMP_SHFL(8, 2) CMP_SHFL(8, 1)
            CMP_SHFL(16, 8) CMP_SHFL(16, 4) CMP_SHFL(16, 2) CMP_SHFL(16, 1)
            CMP_SHFL(32, 16) CMP_SHFL(32, 8) CMP_SHFL(32, 4) CMP_SHFL(32, 2) CMP_SHFL(32, 1)
        }
        __syncthreads();
        if (tx < 128) { bp_s[tx] = v; mi_s[tx] = idx; }
        __syncthreads();
        if (tx < 128) {
            int pj = tx ^ 32;
            float ov = bp_s[pj]; int oidx = mi_s[pj];
            bool amLow = ((tx & 32) == 0);
            float lv = amLow ? v : ov, hv = amLow ? ov : v;
            bool up = ((tx & 64) == 0);
            bool sw = ((lv > hv) == up);
            if (sw) { v = ov; idx = oidx; }
            CMP_SHFL(64, 16) CMP_SHFL(64, 8) CMP_SHFL(64, 4) CMP_SHFL(64, 2) CMP_SHFL(64, 1)
        }
        __syncthreads();
        if (tx < 128) { bp_s[tx] = v; mi_s[tx] = idx; }
        __syncthreads();
        if (tx < 128) {
            int pj = tx ^ 64;
            float ov = bp_s[pj]; int oidx = mi_s[pj];
            bool amLow = ((tx & 64) == 0);
            float lv = amLow ? v : ov, hv = amLow ? ov : v;
            bool sw = (lv > hv);
            if (sw) { v = ov; idx = oidx; }
        }
        __syncthreads();
        if (tx < 128) { bp_s[tx] = v; mi_s[tx] = idx; }
        __syncthreads();
        if (tx < 128) {
            int pj = tx ^ 32;
            float ov = bp_s[pj]; int oidx = mi_s[pj];
            bool amLow = ((tx & 32) == 0);
            float lv = amLow ? v : ov, hv = amLow ? ov : v;
            bool sw = (lv > hv);
            if (sw) { v = ov; idx = oidx; }
            CMP_SHFL(128, 16) CMP_SHFL(128, 8) CMP_SHFL(128, 4) CMP_SHFL(128, 2) CMP_SHFL(128, 1)
        }
        __syncthreads();
        if (tx < 128) { bp_s[tx] = v; mi_s[tx] = idx; }
        #undef CMP_SHFL
    }
    __syncthreads();

    // ---- histogram with cached (s, wt, g) ----
    float sarr[NIT], warr[NIT];
    int   garr[NIT];
    {
        int p0 = warp * PR;
        int pend = min(p0 + PR, ROWS);
        #pragma unroll
        for (int it = 0; it < NIT; ++it) {
            int p = p0 + lane + it * 32;
            garr[it] = -1;
            if (p < pend) {
                int i = p / S1, j = p - i * S1;
                float tbi = xb * (steps_s[i] + 1.0f) * 0.5f;
                float rem = xmax - tbi;
                float s = fmaf(rem, (steps_s[j] + 1.0f) * 0.5f, tbi);
                float wt = cc_s[i] * cc_s[j] * rem * 0.5f;
                int g = seg_of(s, bp_s);
                sarr[it] = s; warr[it] = wt; garr[it] = g;
                atomicAdd(&cnt2[warp * 132 + g], 1);
            }
        }
    }
    __syncthreads();

    // ---- parallel exclusive scan of segment counts ----
    int tcnt = 0;
    if (tx < 129) {
        #pragma unroll
        for (int w = 0; w < 8; w++) tcnt += cnt2[w * 132 + tx];
        offs_s[tx] = tcnt;
    }
    __syncthreads();
    #pragma unroll
    for (int d = 1; d <= 128; d <<= 1) {
        int add = 0;
        if (tx < 129 && tx >= d) add = offs_s[tx - d];
        __syncthreads();
        if (tx < 129) offs_s[tx] += add;
        __syncthreads();
    }
    if (tx < 129) offs_s[tx] -= tcnt;          // exclusive
    __syncthreads();
    if (tx < 129) g_offs[b * 130 + tx] = offs_s[tx];
    if (tx == 0)  g_offs[b * 130 + 129] = ROWS;
    if (tx < 129) {
        int run = offs_s[tx];
        #pragma unroll
        for (int w = 0; w < 8; w++) { woff[w * 132 + tx] = run; run += cnt2[w * 132 + tx]; }
    }
    __syncthreads();

    // ---- deterministic scatter using cached values ----
    {
        int* myoff = woff + warp * 132;
        #pragma unroll
        for (int it = 0; it < NIT; ++it) {
            bool valid = (garr[it] >= 0);
            int g = valid ? garr[it] : (512 + lane);
            unsigned mm = __match_any_sync(0xffffffffu, g);
            int rank_in = __popc(mm & ((1u << lane) - 1u));
            int leader = __ffs(mm) - 1;
            int boff = 0;
            if (lane == leader && valid) {
                boff = myoff[g];
                myoff[g] = boff + __popc(mm);
            }
            boff = __shfl_sync(0xffffffffu, boff, leader);
            if (valid)
                g_meta[b * ROWS + boff + rank_in] =
                    make_float4(sarr[it], warr[it], __int_as_float(g), 0.0f);
        }
    }

    // ---- single-pass builder (stores only) ----
    {
        const int k = tx & 127;
        const bool isA = (tx < 128);
        const int kp = iperm_s[k];
        const float w2k = iw2_s[k];
        float* segb = g_AB + (size_t)b * SEGB;
        const int fidx = ((kp >> 2) << 3) + (kp & 3) + (isA ? 0 : 4);
        float r = isA ? 0.0f : ib1[k];
        #pragma unroll 8
        for (int m = 0; m < HID; ++m) {
            float w0m = w0_s[m];
            float coef = isA ? w0m : base_s[m];
            coef = (w0m <= 0.0f) ? coef : 0.0f;
            r = fmaf(coef, __ldg(&iw1[(m << 7) + k]), r);
        }
        segb[fidx] = r * w2k;
        #pragma unroll 8
        for (int g = 0; g < 128; ++g) {
            int m = mi_s[g];
            float w0m = w0_s[m];
            float coef = isA ? w0m : base_s[m];
            float csel = (w0m > 0.0f) ? coef : -coef;
            r = fmaf(csel, __ldg(&iw1[(m << 7) + k]), r);
            segb[(g + 1) * SEGROW + fidx] = r * w2k;
        }
    }
    // zero pad slots
    {
        int d = nposp - npos;
        float* segb = g_AB + (size_t)b * SEGB;
        for (int idx = tx; idx < 129 * 8; idx += 256) {
            int g = idx >> 3, e = idx & 7;
            int sl = (e < d) ? (npos + e) : (nposp + (HID - npos) + (e - d));
            int fa = g * SEGROW + ((sl >> 2) << 3) + (sl & 3);
            segb[fa] = 0.0f;
            segb[fa + 4] = 0.0f;
        }
    }
}

// ===================== quad: strip-staged smem rows, 5 blocks/SM =====================
__global__ void __launch_bounds__(256, 5)
quad_kernel(const float* __restrict__ x, const float* __restrict__ ib2,
            float* __restrict__ out)
{
    __shared__ float4 rows_s[SMAX * (SEGROW / 4)];
    __shared__ float red_s[256];
    __shared__ int info_s[2];

    const int b     = blockIdx.x >> 2;     // CPB = 4
    const int chunk = blockIdx.x & 3;
    const int tx    = threadIdx.x;
    const int np4   = g_nposp >> 2;
    const float ib2v = __ldg(ib2);

    const float4* ABb   = (const float4*)(g_AB + (size_t)b * SEGB);
    const float4* metab = &g_meta[b * ROWS];

    const int q0   = chunk * PPC;
    const int qend = min(q0 + PPC, ROWS);

    float acc = 0.0f;
    int qcur = q0;
    while (qcur < qend) {
        __syncthreads();
        if (tx == 0) {
            float4 m0 = __ldg(&metab[qcur]);
            int gb = __float_as_int(m0.z);
            info_s[0] = gb;
            int ghi = min(gb + SMAX, 129);
            info_s[1] = g_offs[b * 130 + ghi];
        }
        __syncthreads();
        const int g_base = info_s[0];
        const int NR = min(g_base + SMAX, 129) - g_base;
        const int strip_end = min(info_s[1], qend);
        const float4* src = ABb + g_base * (SEGROW / 4);
        for (int i = tx; i < NR * (SEGROW / 4); i += 256)
            rows_s[i] = __ldg(src + i);
        __syncthreads();

        for (int q = qcur + tx; q < strip_end; q += 256) {
            float4 m = __ldg(&metab[q]);
            const float4* row = rows_s + (__float_as_int(m.z) - g_base) * (SEGROW / 4);
            float s = m.x;
            float pr0 = 0.0f, pr1 = 0.0f;
            int kq = 0;
            #pragma unroll 4
            for (; kq < np4; ++kq) {
                float4 a = row[2 * kq], bb = row[2 * kq + 1];
                pr0 += fmaxf(fmaf(s, a.x, bb.x), 0.0f) + fmaxf(fmaf(s, a.y, bb.y), 0.0f);
                pr1 += fmaxf(fmaf(s, a.z, bb.z), 0.0f) + fmaxf(fmaf(s, a.w, bb.w), 0.0f);
            }
            #pragma unroll 4
            for (; kq < NK4; ++kq) {
                float4 a = row[2 * kq], bb = row[2 * kq + 1];
                pr0 += fminf(fmaf(s, a.x, bb.x), 0.0f) + fminf(fmaf(s, a.y, bb.y), 0.0f);
                pr1 += fminf(fmaf(s, a.z, bb.z), 0.0f) + fminf(fmaf(s, a.w, bb.w), 0.0f);
            }
            float z = (pr0 + pr1) + ib2v;
            float f = (z > 0.0f) ? (z + 1.0f) : __expf(z);   // elu(z)+1
            acc = fmaf(f, m.y, acc);
        }
        qcur = strip_end;
    }

    red_s[tx] = acc;
    __syncthreads();
    for (int o = 128; o > 0; o >>= 1) {
        if (tx < o) red_s[tx] += red_s[tx + o];
        __syncthreads();
    }
    if (tx == 0) {
        g_part[b * CPB + chunk] = red_s[0];
        __threadfence();
        int old = atomicAdd(&g_done[b], 1);
        if (old == CPB - 1) {
            __threadfence();
            float sum = 0.0f;
            #pragma unroll
            for (int c = 0; c < CPB; c++) sum += __ldcg(&g_part[b * CPB + c]);
            float outer = sum * __ldg(&x[b]) * 0.5f;
            out[b] = expf(__ldcg(&g_osc[2 * b + 1])) * outer + __ldcg(&g_osc[2 * b]);
        }
    }
}

// ===================== launch =====================
extern "C" void kernel_launch(void* const* d_in, const int* in_sizes, int n_in,
                              void* d_out, int out_size) {
    const float* x   = (const float*)d_in[0];
    const float* h   = (const float*)d_in[1];
    const float* iw0 = (const float*)d_in[2];
    const float* ib0 = (const float*)d_in[3];
    const float* iw1 = (const float*)d_in[4];
    const float* ib1 = (const float*)d_in[5];
    const float* iw2 = (const float*)d_in[6];
    const float* ib2 = (const float*)d_in[7];
    const float* nw0 = (const float*)d_in[8];
    const float* nb0 = (const float*)d_in[9];
    const float* nw1 = (const float*)d_in[10];
    const float* nb1 = (const float*)d_in[11];
    const float* nw2 = (const float*)d_in[12];
    const float* nb2 = (const float*)d_in[13];
    float* out = (float*)d_out;
    (void)in_sizes; (void)n_in; (void)out_size;

    build_kernel<<<BSZ, 256>>>(x, h, iw0, ib0, iw1, ib1, iw2,
                               nw0, nb0, nw1, nb1, nw2, nb2);
    quad_kernel<<<BSZ * CPB, 256>>>(x, ib2, out);
}

// round 17
// speedup vs baseline: 1.0901x; 1.0901x over previous
#include <cuda_runtime.h>
#include <math.h>

#define BSZ 256
#define IND 64
#define HID 128
#define NB 50
#define S1 51
#define ROWS (S1 * S1)            // 2601
#define SEGROW 272                // interleaved A/B row: 34 * (A4 + B4) floats
#define NK4 34
#define SEGB (129 * SEGROW)       // 35088 floats per b
#define CPB 4
#define PPC ((ROWS + CPB - 1) / CPB)   // 651
#define BT  512                   // build threads
#define NW  16                    // build warps
#define PR  163                   // points per scatter-warp (16 warps)
#define NIT 6                     // ceil(PR/32)
#define SMAX 40                   // max segment rows staged per strip
#define TH0 0.06283185307179586f  // pi/50

// ---------------- global scratch ----------------
__device__ int   g_nposp;
__device__ __align__(16) float g_AB[BSZ * SEGB];   // ~36 MB interleaved A/B
__device__ float4 g_meta[BSZ * ROWS];
__device__ int   g_offs[BSZ * 130];
__device__ float g_part[BSZ * CPB];
__device__ float g_osc[BSZ * 2];
__device__ int   g_done[BSZ];

__device__ __forceinline__ int seg_of(float s, const float* bp_s) {
    int g = 0;
    #pragma unroll
    for (int stp = 64; stp >= 1; stp >>= 1) {
        int cand = g + stp;
        if (cand <= 128 && bp_s[cand - 1] < s) g = cand;
    }
    return g;
}

// ===================== build: 512 threads =====================
__global__ void __launch_bounds__(BT, 2)
build_kernel(const float* __restrict__ x,   const float* __restrict__ h,
             const float* __restrict__ iw0, const float* __restrict__ ib0,
             const float* __restrict__ iw1, const float* __restrict__ ib1,
             const float* __restrict__ iw2,
             const float* __restrict__ nw0, const float* __restrict__ nb0,
             const float* __restrict__ nw1, const float* __restrict__ nb1,
             const float* __restrict__ nw2, const float* __restrict__ nb2)
{
    __shared__ float h_s[64];
    __shared__ float base_s[HID];
    __shared__ float w0_s[HID];
    __shared__ float bp_s[HID];
    __shared__ int   mi_s[HID];
    __shared__ float iw2_s[HID];
    __shared__ int   iperm_s[HID];
    __shared__ float a_s[HID];
    __shared__ float a2_s[HID];
    __shared__ float red_s[8];
    __shared__ float steps_s[S1 + 1];
    __shared__ float cc_s[S1 + 1];
    __shared__ float redx_s[256];
    __shared__ int   cnt2[NW * 132];
    __shared__ int   woff[NW * 132];
    __shared__ int   offs_s[132];
    __shared__ int   wc_s[4];
    __shared__ int   npos_s, nposp_s;
    __shared__ float xmax_s;

    const int tx = threadIdx.x;
    const int warp = tx >> 5, lane = tx & 31;
    const int b  = blockIdx.x;
    const float xb = x[b];

    if (tx < IND - 1) h_s[tx] = h[b * (IND - 1) + tx];
    if (tx < HID) iw2_s[tx] = iw2[tx];
    for (int i = tx; i < NW * 132; i += BT) cnt2[i] = 0;
    if (tx == 0) g_done[b] = 0;

    // xmax (first 256 threads hold x; others just hit barriers)
    if (tx < 256) redx_s[tx] = x[tx];
    __syncthreads();
    for (int o = 128; o > 0; o >>= 1) {
        if (tx < o) redx_s[tx] = fmaxf(redx_s[tx], redx_s[tx + o]);
        __syncthreads();
    }
    if (tx == 0) xmax_s = fmaxf(redx_s[0], 0.0f) + 10.0f;

    // steps + cc
    if (tx < S1) steps_s[tx] = cosf((float)tx * TH0);
    __syncthreads();
    if (tx < S1) {
        float sv = steps_s[tx];
        float c1 = fmaf(2.0f * sv, sv, -1.0f);
        float cm2 = 1.0f, cm1 = c1;
        float sum = 1.0f;
        #pragma unroll
        for (int ie = 1; ie <= 25; ++ie) {
            float cv = (ie == 1) ? c1 : fmaf(2.0f * c1, cm1, -cm2);
            if (ie > 1) { cm2 = cm1; cm1 = cv; }
            float W = 2.0f / (1.0f - 4.0f * (float)(ie * ie));
            sum = fmaf(cv, W, sum);
        }
        float v = sum * (2.0f / (float)NB);
        if (tx == 0 || tx == NB) v *= 0.5f;
        cc_s[tx] = v;
    }

    // iperm via ballot scan (warps 0-3)
    {
        bool pos = false; unsigned bal = 0;
        if (tx < HID) {
            pos = (iw2_s[tx] >= 0.0f);
            bal = __ballot_sync(0xffffffffu, pos);
            if (lane == 0) wc_s[warp] = __popc(bal);
        }
        __syncthreads();
        if (tx == 0) {
            int np = wc_s[0] + wc_s[1] + wc_s[2] + wc_s[3];
            npos_s = np;
            nposp_s = (np + 3) & ~3;
            if (b == 0) g_nposp = nposp_s;
        }
        __syncthreads();
        if (tx < HID) {
            unsigned lt = (1u << lane) - 1u;
            int posbef = __popc(bal & lt);
            int prefpos = 0;
            #pragma unroll
            for (int wi = 0; wi < 4; ++wi) if (wi < warp) prefpos += wc_s[wi];
            int slot;
            if (pos) slot = prefpos + posbef;
            else     slot = nposp_s + (warp * 32 - prefpos) + (lane - posbef);
            iperm_s[tx] = slot;
        }
    }

    const float xmax = xmax_s;
    const int npos  = npos_s;
    const int nposp = nposp_s;

    // base/breakpoints (tx<128) | nmlp layer0 (128..255)
    if (tx < HID) {
        float acc = ib0[tx];
        #pragma unroll 7
        for (int d = 0; d < IND - 1; ++d)
            acc = fmaf(h_s[d], iw0[(d + 1) * HID + tx], acc);
        base_s[tx] = acc;
        float w0m = iw0[tx];
        w0_s[tx] = w0m;
        float ss;
        if (w0m != 0.0f) ss = -acc / w0m;
        else ss = (acc > 0.0f) ? __int_as_float(0x7f800000) : __int_as_float(0xff800000);
        bp_s[tx] = ss;
    } else if (tx < 256) {
        int k = tx - 128;
        float acc = nb0[k];
        #pragma unroll 7
        for (int d = 0; d < IND - 1; ++d)
            acc = fmaf(h_s[d], nw0[d * HID + k], acc);
        a_s[k] = fmaxf(acc, 0.0f);
    }
    __syncthreads();
    // nmlp layer1: 2 threads per output (halved chain)
    if (tx < 256) {
        int k = tx >> 1, half = tx & 1;
        int m0 = half << 6;
        float acc = 0.0f;
        #pragma unroll 8
        for (int m = m0; m < m0 + 64; ++m)
            acc = fmaf(a_s[m], nw1[m * HID + k], acc);
        acc += __shfl_xor_sync(0xffffffffu, acc, 1);
        if (half == 0) a2_s[k] = fmaxf(acc + nb1[k], 0.0f);
    }
    __syncthreads();
    if (tx < 256) {
        int o  = tx >> 7;
        int n2 = tx & 127;
        float p = a2_s[n2] * nw2[n2 * 2 + o];
        #pragma unroll
        for (int off = 16; off >= 1; off >>= 1)
            p += __shfl_xor_sync(0xffffffffu, p, off);
        if (lane == 0) red_s[warp] = p;
    }
    __syncthreads();
    if (tx == 0)   g_osc[2 * b]     = nb2[0] + ((red_s[0] + red_s[1]) + (red_s[2] + red_s[3]));
    if (tx == 128) g_osc[2 * b + 1] = nb2[1] + ((red_s[4] + red_s[5]) + (red_s[6] + red_s[7]));

    // ---- bitonic sort of 128 breakpoints: registers + shfl, 3 smem steps ----
    {
        float v = 0.0f; int idx = 0;
        if (tx < 128) { v = bp_s[tx]; idx = tx; }

        #define CMP_SHFL(kkc, jc) { \
            float ov = __shfl_xor_sync(0xffffffffu, v, (jc)); \
            int oidx = __shfl_xor_sync(0xffffffffu, idx, (jc)); \
            bool amLow = ((tx & (jc)) == 0); \
            float lv = amLow ? v : ov, hv = amLow ? ov : v; \
            bool up = ((tx & (kkc)) == 0); \
            bool sw = ((lv > hv) == up); \
            if (sw) { v = ov; idx = oidx; } }

        if (tx < 128) {
            CMP_SHFL(2, 1)
            CMP_SHFL(4, 2) CMP_SHFL(4, 1)
            CMP_SHFL(8, 4) CMP_SHFL(8, 2) CMP_SHFL(8, 1)
            CMP_SHFL(16, 8) CMP_SHFL(16, 4) CMP_SHFL(16, 2) CMP_SHFL(16, 1)
            CMP_SHFL(32, 16) CMP_SHFL(32, 8) CMP_SHFL(32, 4) CMP_SHFL(32, 2) CMP_SHFL(32, 1)
        }
        __syncthreads();
        if (tx < 128) { bp_s[tx] = v; mi_s[tx] = idx; }
        __syncthreads();
        if (tx < 128) {
            int pj = tx ^ 32;
            float ov = bp_s[pj]; int oidx = mi_s[pj];
            bool amLow = ((tx & 32) == 0);
            float lv = amLow ? v : ov, hv = amLow ? ov : v;
            bool up = ((tx & 64) == 0);
            bool sw = ((lv > hv) == up);
            if (sw) { v = ov; idx = oidx; }
            CMP_SHFL(64, 16) CMP_SHFL(64, 8) CMP_SHFL(64, 4) CMP_SHFL(64, 2) CMP_SHFL(64, 1)
        }
        __syncthreads();
        if (tx < 128) { bp_s[tx] = v; mi_s[tx] = idx; }
        __syncthreads();
        if (tx < 128) {
            int pj = tx ^ 64;
            float ov = bp_s[pj]; int oidx = mi_s[pj];
            bool amLow = ((tx & 64) == 0);
            float lv = amLow ? v : ov, hv = amLow ? ov : v;
            bool sw = (lv > hv);
            if (sw) { v = ov; idx = oidx; }
        }
        __syncthreads();
        if (tx < 128) { bp_s[tx] = v; mi_s[tx] = idx; }
        __syncthreads();
        if (tx < 128) {
            int pj = tx ^ 32;
            float ov = bp_s[pj]; int oidx = mi_s[pj];
            bool amLow = ((tx & 32) == 0);
            float lv = amLow ? v : ov, hv = amLow ? ov : v;
            bool sw = (lv > hv);
            if (sw) { v = ov; idx = oidx; }
            CMP_SHFL(128, 16) CMP_SHFL(128, 8) CMP_SHFL(128, 4) CMP_SHFL(128, 2) CMP_SHFL(128, 1)
        }
        __syncthreads();
        if (tx < 128) { bp_s[tx] = v; mi_s[tx] = idx; }
        #undef CMP_SHFL
    }
    __syncthreads();

    // ---- histogram with cached (s, wt, g): 16 warps ----
    float sarr[NIT], warr[NIT];
    int   garr[NIT];
    {
        int p0 = warp * PR;
        int pend = min(p0 + PR, ROWS);
        #pragma unroll
        for (int it = 0; it < NIT; ++it) {
            int p = p0 + lane + it * 32;
            garr[it] = -1;
            if (p < pend) {
                int i = p / S1, j = p - i * S1;
                float tbi = xb * (steps_s[i] + 1.0f) * 0.5f;
                float rem = xmax - tbi;
                float s = fmaf(rem, (steps_s[j] + 1.0f) * 0.5f, tbi);
                float wt = cc_s[i] * cc_s[j] * rem * 0.5f;
                int g = seg_of(s, bp_s);
                sarr[it] = s; warr[it] = wt; garr[it] = g;
                atomicAdd(&cnt2[warp * 132 + g], 1);
            }
        }
    }
    __syncthreads();

    // ---- parallel exclusive scan of segment counts ----
    int tcnt = 0;
    if (tx < 129) {
        #pragma unroll
        for (int w = 0; w < NW; w++) tcnt += cnt2[w * 132 + tx];
        offs_s[tx] = tcnt;
    }
    __syncthreads();
    #pragma unroll
    for (int d = 1; d <= 128; d <<= 1) {
        int add = 0;
        if (tx < 129 && tx >= d) add = offs_s[tx - d];
        __syncthreads();
        if (tx < 129) offs_s[tx] += add;
        __syncthreads();
    }
    if (tx < 129) offs_s[tx] -= tcnt;          // exclusive
    __syncthreads();
    if (tx < 129) g_offs[b * 130 + tx] = offs_s[tx];
    if (tx == 0)  g_offs[b * 130 + 129] = ROWS;
    if (tx < 129) {
        int run = offs_s[tx];
        #pragma unroll
        for (int w = 0; w < NW; w++) { woff[w * 132 + tx] = run; run += cnt2[w * 132 + tx]; }
    }
    __syncthreads();

    // ---- deterministic scatter using cached values ----
    {
        int* myoff = woff + warp * 132;
        #pragma unroll
        for (int it = 0; it < NIT; ++it) {
            bool valid = (garr[it] >= 0);
            int g = valid ? garr[it] : (512 + lane);
            unsigned mm = __match_any_sync(0xffffffffu, g);
            int rank_in = __popc(mm & ((1u << lane) - 1u));
            int leader = __ffs(mm) - 1;
            int boff = 0;
            if (lane == leader && valid) {
                boff = myoff[g];
                myoff[g] = boff + __popc(mm);
            }
            boff = __shfl_sync(0xffffffffu, boff, leader);
            if (valid)
                g_meta[b * ROWS + boff + rank_in] =
                    make_float4(sarr[it], warr[it], __int_as_float(g), 0.0f);
        }
    }

    // ---- single-pass builder (tx<256) | pad zeroing (tx>=256), concurrent ----
    if (tx < 256) {
        const int k = tx & 127;
        const bool isA = (tx < 128);
        const int kp = iperm_s[k];
        const float w2k = iw2_s[k];
        float* segb = g_AB + (size_t)b * SEGB;
        const int fidx = ((kp >> 2) << 3) + (kp & 3) + (isA ? 0 : 4);
        float r = isA ? 0.0f : ib1[k];
        #pragma unroll 8
        for (int m = 0; m < HID; ++m) {
            float w0m = w0_s[m];
            float coef = isA ? w0m : base_s[m];
            coef = (w0m <= 0.0f) ? coef : 0.0f;
            r = fmaf(coef, __ldg(&iw1[(m << 7) + k]), r);
        }
        segb[fidx] = r * w2k;
        #pragma unroll 8
        for (int g = 0; g < 128; ++g) {
            int m = mi_s[g];
            float w0m = w0_s[m];
            float coef = isA ? w0m : base_s[m];
            float csel = (w0m > 0.0f) ? coef : -coef;
            r = fmaf(csel, __ldg(&iw1[(m << 7) + k]), r);
            segb[(g + 1) * SEGROW + fidx] = r * w2k;
        }
    } else {
        int d = nposp - npos;
        float* segb = g_AB + (size_t)b * SEGB;
        for (int idx = tx - 256; idx < 129 * 8; idx += 256) {
            int g = idx >> 3, e = idx & 7;
            int sl = (e < d) ? (npos + e) : (nposp + (HID - npos) + (e - d));
            int fa = g * SEGROW + ((sl >> 2) << 3) + (sl & 3);
            segb[fa] = 0.0f;
            segb[fa + 4] = 0.0f;
        }
    }
}

// ===================== quad: strip-staged smem rows (R13, untouched) =====================
__global__ void __launch_bounds__(256, 4)
quad_kernel(const float* __restrict__ x, const float* __restrict__ ib2,
            float* __restrict__ out)
{
    __shared__ float4 rows_s[SMAX * (SEGROW / 4)];
    __shared__ float red_s[256];
    __shared__ int info_s[2];

    const int b     = blockIdx.x >> 2;     // CPB = 4
    const int chunk = blockIdx.x & 3;
    const int tx    = threadIdx.x;
    const int np4   = g_nposp >> 2;
    const float ib2v = __ldg(ib2);

    const float4* ABb   = (const float4*)(g_AB + (size_t)b * SEGB);
    const float4* metab = &g_meta[b * ROWS];

    const int q0   = chunk * PPC;
    const int qend = min(q0 + PPC, ROWS);

    float acc = 0.0f;
    int qcur = q0;
    while (qcur < qend) {
        __syncthreads();
        if (tx == 0) {
            float4 m0 = __ldg(&metab[qcur]);
            int gb = __float_as_int(m0.z);
            info_s[0] = gb;
            int ghi = min(gb + SMAX, 129);
            info_s[1] = g_offs[b * 130 + ghi];
        }
        __syncthreads();
        const int g_base = info_s[0];
        const int NR = min(g_base + SMAX, 129) - g_base;
        const int strip_end = min(info_s[1], qend);
        const float4* src = ABb + g_base * (SEGROW / 4);
        for (int i = tx; i < NR * (SEGROW / 4); i += 256)
            rows_s[i] = __ldg(src + i);
        __syncthreads();

        for (int q = qcur + tx; q < strip_end; q += 256) {
            float4 m = __ldg(&metab[q]);
            const float4* row = rows_s + (__float_as_int(m.z) - g_base) * (SEGROW / 4);
            float s = m.x;
            float pr0 = 0.0f, pr1 = 0.0f;
            int kq = 0;
            #pragma unroll 4
            for (; kq < np4; ++kq) {
                float4 a = row[2 * kq], bb = row[2 * kq + 1];
                pr0 += fmaxf(fmaf(s, a.x, bb.x), 0.0f) + fmaxf(fmaf(s, a.y, bb.y), 0.0f);
                pr1 += fmaxf(fmaf(s, a.z, bb.z), 0.0f) + fmaxf(fmaf(s, a.w, bb.w), 0.0f);
            }
            #pragma unroll 4
            for (; kq < NK4; ++kq) {
                float4 a = row[2 * kq], bb = row[2 * kq + 1];
                pr0 += fminf(fmaf(s, a.x, bb.x), 0.0f) + fminf(fmaf(s, a.y, bb.y), 0.0f);
                pr1 += fminf(fmaf(s, a.z, bb.z), 0.0f) + fminf(fmaf(s, a.w, bb.w), 0.0f);
            }
            float z = (pr0 + pr1) + ib2v;
            float f = (z > 0.0f) ? (z + 1.0f) : __expf(z);   // elu(z)+1
            acc = fmaf(f, m.y, acc);
        }
        qcur = strip_end;
    }

    red_s[tx] = acc;
    __syncthreads();
    for (int o = 128; o > 0; o >>= 1) {
        if (tx < o) red_s[tx] += red_s[tx + o];
        __syncthreads();
    }
    if (tx == 0) {
        g_part[b * CPB + chunk] = red_s[0];
        __threadfence();
        int old = atomicAdd(&g_done[b], 1);
        if (old == CPB - 1) {
            __threadfence();
            float sum = 0.0f;
            #pragma unroll
            for (int c = 0; c < CPB; c++) sum += __ldcg(&g_part[b * CPB + c]);
            float outer = sum * __ldg(&x[b]) * 0.5f;
            out[b] = expf(__ldcg(&g_osc[2 * b + 1])) * outer + __ldcg(&g_osc[2 * b]);
        }
    }
}

// ===================== launch =====================
extern "C" void kernel_launch(void* const* d_in, const int* in_sizes, int n_in,
                              void* d_out, int out_size) {
    const float* x   = (const float*)d_in[0];
    const float* h   = (const float*)d_in[1];
    const float* iw0 = (const float*)d_in[2];
    const float* ib0 = (const float*)d_in[3];
    const float* iw1 = (const float*)d_in[4];
    const float* ib1 = (const float*)d_in[5];
    const float* iw2 = (const float*)d_in[6];
    const float* ib2 = (const float*)d_in[7];
    const float* nw0 = (const float*)d_in[8];
    const float* nb0 = (const float*)d_in[9];
    const float* nw1 = (const float*)d_in[10];
    const float* nb1 = (const float*)d_in[11];
    const float* nw2 = (const float*)d_in[12];
    const float* nb2 = (const float*)d_in[13];
    float* out = (float*)d_out;
    (void)in_sizes; (void)n_in; (void)out_size;

    build_kernel<<<BSZ, BT>>>(x, h, iw0, ib0, iw1, ib1, iw2,
                              nw0, nb0, nw1, nb1, nw2, nb2);
    quad_kernel<<<BSZ * CPB, 256>>>(x, ib2, out);
}